// round 14
// baseline (speedup 1.0000x reference)
#include <cuda_runtime.h>
#include <cuda_bf16.h>
#include <math.h>
#include <stdint.h>

// Problem constants
#define CB   16
#define CNB  4096
#define CH   128
#define CE   65536
#define CNL  2
constexpr int M_ROWS = CB * CNB;          // 65536
constexpr int XSZ    = CB * CNB * CH;     // 8388608 (x portion of output)

// ---------------- scratch (device globals; no allocations allowed) ---------
__device__ __align__(16) float g_hroute[M_ROWS * CH];
__device__ __align__(16) float g_msg[M_ROWS * CH];
__device__ __align__(16) float g_x[M_ROWS * CH];
__device__ __align__(16) float g_normed[M_ROWS * CH];
__device__ __align__(16) float g_hidden[M_ROWS * 2 * CH];
__device__ int   g_cnt[CNB];
__device__ int   g_cur[CNB];
__device__ int   g_off[CNB + 1];
__device__ int   g_perm[CE];
__device__ int   g_active_bytes;
__device__ int   g_done;

// Pre-transposed/split weights: Wt[n*K + k] as bf16 hi + bf16 lo
constexpr int OFF_P   = 0;                 // N=128,K=128 (16384)
constexpr int OFF_G   = 16384;             // N=128,K=256 (32768)
constexpr int OFF_W1A = 49152;             // N=256,K=128 (32768)
constexpr int OFF_W1B = 81920;
constexpr int OFF_W2A = 114688;            // N=128,K=256 (32768)
constexpr int OFF_W2B = 147456;
constexpr int WT_TOTAL = 180224;
__device__ __align__(16) __nv_bfloat16 g_wth[WT_TOTAL];
__device__ __align__(16) __nv_bfloat16 g_wtl[WT_TOTAL];

// ---------------- helpers --------------------------------------------------
__device__ __forceinline__ float eluf(float v) { return v > 0.f ? v : expm1f(v); }
__device__ __forceinline__ float sigmoidf_(float v) { return 1.f / (1.f + expf(-v)); }

__device__ __forceinline__ bool active_at(const void* p, int idx) {
    if (g_active_bytes == 4) return ((const unsigned*)p)[idx] != 0u;
    return ((const unsigned char*)p)[idx] != 0;
}

// ---------------- fused prep: all weights + CSR zero + dtype detect --------
__global__ void prep_all_kernel(const float* __restrict__ Wp,
                                const float* __restrict__ Wg,
                                const float* __restrict__ W1,
                                const float* __restrict__ W2,
                                const unsigned* __restrict__ active) {
    int i = blockIdx.x * blockDim.x + threadIdx.x;

    // block 0: detect dtype width of block_active + reset done counter
    if (blockIdx.x == 0) {
        __shared__ int bad;
        if (threadIdx.x == 0) { bad = 0; g_done = 0; }
        __syncthreads();
        unsigned w = active[threadIdx.x];
        if (!(w == 0u || w == 1u || w == 0x3F800000u)) atomicAdd(&bad, 1);
        __syncthreads();
        if (threadIdx.x == 0) g_active_bytes = bad ? 1 : 4;
    }

    // CSR counter zeroing (same index space, low range)
    if (i < CNB) { g_cnt[i] = 0; g_cur[i] = 0; }

    if (i >= WT_TOTAL) return;
    // segment lookup (uniform per block: segments are >=16K elements)
    const float* W; int K, N, off;
    if (i < OFF_G)        { W = Wp;                K = 128; N = 128; off = OFF_P; }
    else if (i < OFF_W1A) { W = Wg;                K = 256; N = 128; off = OFF_G; }
    else if (i < OFF_W1B) { W = W1;                K = 128; N = 256; off = OFF_W1A; }
    else if (i < OFF_W2A) { W = W1 + 128 * 256;    K = 128; N = 256; off = OFF_W1B; }
    else if (i < OFF_W2B) { W = W2;                K = 256; N = 128; off = OFF_W2A; }
    else                  { W = W2 + 256 * 128;    K = 256; N = 128; off = OFF_W2B; }
    int li = i - off;
    int n = li / K, k = li - n * K;
    float v = W[(size_t)k * N + n];
    __nv_bfloat16 h = __float2bfloat16(v);
    g_wth[i] = h;
    g_wtl[i] = __float2bfloat16(v - __bfloat162float(h));
}

// ---------------- edge weights: one thread per EDGE, loop over batches -----
// Also builds CSR dst counts (one atomic per edge) and the LAST finished
// block performs the offset scan (replaces the standalone scan_kernel).
__global__ void __launch_bounds__(256) edgew_kernel(
        const float* __restrict__ es,
        const float* __restrict__ ct_emb,
        const int* __restrict__ ctype,
        const int* __restrict__ esrc,
        const int* __restrict__ edst,
        const void* __restrict__ active,
        float* __restrict__ ew_out) {
    __shared__ int ct[CB];
    __shared__ int lastf;
    __shared__ int wsum[8];
    int tid = threadIdx.x;
    if (tid < CB) ct[tid] = ctype[tid];
    __syncthreads();

    int e = blockIdx.x * 256 + tid;   // e < CE (grid = CE/256)
    int src = esrc[e], dst = edst[e];
    atomicAdd(&g_cnt[dst], 1);
    float s = sigmoidf_(es[e]);
    #pragma unroll 4
    for (int b = 0; b < CB; b++) {
        float w = s * ct_emb[(size_t)ct[b] * CE + e];
        bool as = active_at(active, b * CNB + src);
        bool ad = active_at(active, b * CNB + dst);
        ew_out[(size_t)b * CE + e] = (as && ad) ? w : 0.f;
    }

    // ---- last-block CSR offset scan ----
    __threadfence();
    __syncthreads();
    if (tid == 0) lastf = (atomicAdd(&g_done, 1) == (int)gridDim.x - 1);
    __syncthreads();
    if (!lastf) return;

    // 256 threads scan 4096 counters: 16 serial each + 2-level shuffle scan
    int base = tid * 16;
    int v[16], sum = 0;
    #pragma unroll
    for (int q = 0; q < 16; q++) { v[q] = g_cnt[base + q]; sum += v[q]; }
    int lane = tid & 31, wrp = tid >> 5;
    int pre = sum;
    #pragma unroll
    for (int o = 1; o < 32; o <<= 1) {
        int x = __shfl_up_sync(0xffffffffu, pre, o);
        if (lane >= o) pre += x;
    }
    if (lane == 31) wsum[wrp] = pre;
    __syncthreads();
    if (wrp == 0) {
        int wv = (lane < 8) ? wsum[lane] : 0;
        #pragma unroll
        for (int o = 1; o < 8; o <<= 1) {
            int x = __shfl_up_sync(0xffffffffu, wv, o);
            if (lane >= o) wv += x;
        }
        if (lane < 8) wsum[lane] = wv;
    }
    __syncthreads();
    int excl = pre - sum + (wrp ? wsum[wrp - 1] : 0);   // exclusive prefix
    #pragma unroll
    for (int q = 0; q < 16; q++) { g_off[base + q] = excl; excl += v[q]; }
    if (tid == 255) g_off[CNB] = excl;
}

// ---------------- CSR fill --------------------------------------------------
__global__ void fill_kernel(const int* __restrict__ edst) {
    int e = blockIdx.x * blockDim.x + threadIdx.x;
    if (e >= CE) return;
    int d = edst[e];
    int pos = g_off[d] + atomicAdd(&g_cur[d], 1);
    g_perm[pos] = e;
}

// ---------------- message gather (one warp per (b, node)) ------------------
__global__ void messages_kernel(const float* __restrict__ edge_w,
                                const int* __restrict__ esrc) {
    int gw = (blockIdx.x * blockDim.x + threadIdx.x) >> 5;
    int lane = threadIdx.x & 31;
    if (gw >= CB * CNB) return;
    int b = gw >> 12;
    int n = gw & (CNB - 1);
    const float* hb  = g_hroute + (size_t)b * CNB * CH;
    const float* ewb = edge_w + (size_t)b * CE;
    float4 acc = make_float4(0.f, 0.f, 0.f, 0.f);
    int s = g_off[n], e = g_off[n + 1];
    for (int j = s; j < e; j++) {
        int eid = g_perm[j];
        float w = ewb[eid];
        const float4* src4 = (const float4*)(hb + (size_t)esrc[eid] * CH);
        float4 v = src4[lane];
        acc.x += w * v.x; acc.y += w * v.y; acc.z += w * v.z; acc.w += w * v.w;
    }
    ((float4*)(g_msg + (size_t)gw * CH))[lane] = acc;
}

// ---------------- LayerNorm ------------------------------------------------
__global__ void ln_kernel(const float* __restrict__ x,
                          const float* __restrict__ scale,
                          const float* __restrict__ bias,
                          float* __restrict__ out) {
    int row = (blockIdx.x * blockDim.x + threadIdx.x) >> 5;
    int lane = threadIdx.x & 31;
    if (row >= M_ROWS) return;
    const float4* xr = (const float4*)(x + (size_t)row * CH);
    float4 v = xr[lane];
    float s = v.x + v.y + v.z + v.w;
    #pragma unroll
    for (int o = 16; o; o >>= 1) s += __shfl_xor_sync(0xffffffffu, s, o);
    float mu = s * (1.f / CH);
    float dx = v.x - mu, dy = v.y - mu, dz = v.z - mu, dw = v.w - mu;
    float ss = dx * dx + dy * dy + dz * dz + dw * dw;
    #pragma unroll
    for (int o = 16; o; o >>= 1) ss += __shfl_xor_sync(0xffffffffu, ss, o);
    float inv = rsqrtf(ss * (1.f / CH) + 1e-5f);
    float4 sc = ((const float4*)scale)[lane];
    float4 bi = ((const float4*)bias)[lane];
    float4 o4;
    o4.x = dx * inv * sc.x + bi.x;
    o4.y = dy * inv * sc.y + bi.y;
    o4.z = dz * inv * sc.z + bi.z;
    o4.w = dw * inv * sc.w + bi.w;
    ((float4*)(out + (size_t)row * CH))[lane] = o4;
}

// ---------------- tensor-core GEMM (mma.sync, bf16 hi/lo, R6 schedule) -----
// C[M,N] = epi(A@Wt^T + bias), BM=BN=128, KC=64, 256 threads (8 warps),
// warp tile 32x64, m16n8k16. A: f32 load + in-loop hi/lo convert.
// B: pre-split bf16 uint4 fill.
// MODE 0: ELU   MODE 1: out = aux0 + sigmoid(v)*aux1   MODE 2: out = aux0 + v

__device__ __forceinline__ void mma16816(float* d, const uint32_t* a, const uint32_t* b) {
    asm volatile(
        "mma.sync.aligned.m16n8k16.row.col.f32.bf16.bf16.f32 "
        "{%0,%1,%2,%3}, {%4,%5,%6,%7}, {%8,%9}, {%0,%1,%2,%3};\n"
        : "+f"(d[0]), "+f"(d[1]), "+f"(d[2]), "+f"(d[3])
        : "r"(a[0]), "r"(a[1]), "r"(a[2]), "r"(a[3]), "r"(b[0]), "r"(b[1]));
}

constexpr int LDT   = 72;                   // padded row length (bf16 elems)
constexpr int GK_AH = 0;                    // 128 x 72 x 2B = 18432 each
constexpr int GK_AL = 18432;
constexpr int GK_BH = 36864;
constexpr int GK_BL = 55296;
constexpr int GK_SMEM = 73728;

template <int MODE>
__global__ void __launch_bounds__(256) mma_gemm_kernel(
    const float* __restrict__ A0, const float* __restrict__ A1, int K0, int K,
    const __nv_bfloat16* __restrict__ Wth, const __nv_bfloat16* __restrict__ Wtl,
    const float* __restrict__ bias,
    float* __restrict__ C, int N,
    const float* __restrict__ aux0, const float* __restrict__ aux1) {
    extern __shared__ __align__(16) char sm[];
    const int tid = threadIdx.x;
    const int wid = tid >> 5, lane = tid & 31;
    const int g = lane >> 2, tig = lane & 3;
    const int wm = (wid & 3) * 32, wn = (wid >> 2) * 64;
    const int bm = blockIdx.y * 128, bn = blockIdx.x * 128;

    float acc[2][8][4];
    #pragma unroll
    for (int i = 0; i < 2; i++)
        #pragma unroll
        for (int j = 0; j < 8; j++)
            #pragma unroll
            for (int q = 0; q < 4; q++) acc[i][j][q] = 0.f;

    for (int kc = 0; kc < K; kc += 64) {
        const float* Ap; int lda, kk;
        if (kc < K0) { Ap = A0; lda = K0; kk = kc; }
        else         { Ap = A1; lda = K - K0; kk = kc - K0; }
        // A tile: 128 rows x 64 cols fp32 -> bf16 hi/lo in SMEM
        #pragma unroll
        for (int it = 0; it < 8; it++) {
            int i = tid + it * 256;
            int row = i >> 4, c4 = (i & 15) << 2;
            float4 v = *(const float4*)(Ap + (size_t)(bm + row) * lda + kk + c4);
            __nv_bfloat162 h0, h1, l0, l1;
            h0.x = __float2bfloat16(v.x); h0.y = __float2bfloat16(v.y);
            h1.x = __float2bfloat16(v.z); h1.y = __float2bfloat16(v.w);
            l0.x = __float2bfloat16(v.x - __bfloat162float(h0.x));
            l0.y = __float2bfloat16(v.y - __bfloat162float(h0.y));
            l1.x = __float2bfloat16(v.z - __bfloat162float(h1.x));
            l1.y = __float2bfloat16(v.w - __bfloat162float(h1.y));
            int off = (row * LDT + c4) * 2;
            *(__nv_bfloat162*)(sm + GK_AH + off)     = h0;
            *(__nv_bfloat162*)(sm + GK_AH + off + 4) = h1;
            *(__nv_bfloat162*)(sm + GK_AL + off)     = l0;
            *(__nv_bfloat162*)(sm + GK_AL + off + 4) = l1;
        }
        // B tile: 128 n-rows x 64 k-cols, pre-split bf16, uint4 moves
        #pragma unroll
        for (int it = 0; it < 4; it++) {
            int i = tid + it * 256;
            int n = i >> 3, k8 = (i & 7) << 3;
            size_t src = (size_t)(bn + n) * K + kc + k8;
            int off = (n * LDT + k8) * 2;
            *(uint4*)(sm + GK_BH + off) = *(const uint4*)(Wth + src);
            *(uint4*)(sm + GK_BL + off) = *(const uint4*)(Wtl + src);
        }
        __syncthreads();

        #pragma unroll
        for (int ks = 0; ks < 4; ks++) {
            int k0 = ks << 4;
            uint32_t ah[2][4], al[2][4];
            #pragma unroll
            for (int mt = 0; mt < 2; mt++) {
                int r0 = wm + mt * 16 + g;
                int o0 = (r0 * LDT + k0 + tig * 2) * 2;
                int o1 = ((r0 + 8) * LDT + k0 + tig * 2) * 2;
                ah[mt][0] = *(const uint32_t*)(sm + GK_AH + o0);
                ah[mt][1] = *(const uint32_t*)(sm + GK_AH + o1);
                ah[mt][2] = *(const uint32_t*)(sm + GK_AH + o0 + 16);
                ah[mt][3] = *(const uint32_t*)(sm + GK_AH + o1 + 16);
                al[mt][0] = *(const uint32_t*)(sm + GK_AL + o0);
                al[mt][1] = *(const uint32_t*)(sm + GK_AL + o1);
                al[mt][2] = *(const uint32_t*)(sm + GK_AL + o0 + 16);
                al[mt][3] = *(const uint32_t*)(sm + GK_AL + o1 + 16);
            }
            #pragma unroll
            for (int nt = 0; nt < 8; nt++) {
                int nb = wn + nt * 8 + g;
                int ob = (nb * LDT + k0 + tig * 2) * 2;
                uint32_t bh[2], bl[2];
                bh[0] = *(const uint32_t*)(sm + GK_BH + ob);
                bh[1] = *(const uint32_t*)(sm + GK_BH + ob + 16);
                bl[0] = *(const uint32_t*)(sm + GK_BL + ob);
                bl[1] = *(const uint32_t*)(sm + GK_BL + ob + 16);
                #pragma unroll
                for (int mt = 0; mt < 2; mt++) {
                    mma16816(acc[mt][nt], ah[mt], bh);
                    mma16816(acc[mt][nt], ah[mt], bl);
                    mma16816(acc[mt][nt], al[mt], bh);
                }
            }
        }
        __syncthreads();
    }

    // epilogue: c0,c1 -> row g; c2,c3 -> row g+8; cols tig*2, tig*2+1
    #pragma unroll
    for (int mt = 0; mt < 2; mt++) {
        #pragma unroll
        for (int half = 0; half < 2; half++) {
            int r = bm + wm + mt * 16 + g + half * 8;
            #pragma unroll
            for (int nt = 0; nt < 8; nt++) {
                int col = bn + wn + nt * 8 + tig * 2;
                float v0 = acc[mt][nt][half * 2 + 0];
                float v1 = acc[mt][nt][half * 2 + 1];
                float2 bv = *(const float2*)(bias + col);
                v0 += bv.x; v1 += bv.y;
                size_t idx = (size_t)r * N + col;
                if (MODE == 0) {
                    v0 = eluf(v0); v1 = eluf(v1);
                } else if (MODE == 1) {
                    float2 a0v = *(const float2*)(aux0 + idx);
                    float2 a1v = *(const float2*)(aux1 + idx);
                    v0 = a0v.x + sigmoidf_(v0) * a1v.x;
                    v1 = a0v.y + sigmoidf_(v1) * a1v.y;
                } else {
                    float2 a0v = *(const float2*)(aux0 + idx);
                    v0 = a0v.x + v0; v1 = a0v.y + v1;
                }
                *(float2*)(C + idx) = make_float2(v0, v1);
            }
        }
    }
}

// ---------------- launch ----------------------------------------------------
extern "C" void kernel_launch(void* const* d_in, const int* in_sizes, int n_in,
                              void* d_out, int out_size) {
    const float* bt     = (const float*)d_in[0];
    const float* es     = (const float*)d_in[1];
    const float* ct_emb = (const float*)d_in[2];
    const float* Wp     = (const float*)d_in[3];
    const float* bp     = (const float*)d_in[4];
    const float* Wg     = (const float*)d_in[5];
    const float* bg     = (const float*)d_in[6];
    const float* lns    = (const float*)d_in[7];
    const float* lnb    = (const float*)d_in[8];
    const float* W1     = (const float*)d_in[9];
    const float* b1     = (const float*)d_in[10];
    const float* W2     = (const float*)d_in[11];
    const float* b2     = (const float*)d_in[12];
    const int*   ctype  = (const int*)d_in[13];
    const int*   esrc   = (const int*)d_in[14];
    const int*   edst   = (const int*)d_in[15];
    const void*  active = d_in[16];

    float* out_x  = (float*)d_out;
    float* out_ew = out_x + XSZ;

    void *pv;
    #define SYM(name, var, type) cudaGetSymbolAddress(&pv, name); type* var = (type*)pv;
    SYM(g_hroute, hroute, float) SYM(g_msg, msg, float)
    SYM(g_x, xbuf, float) SYM(g_normed, normed, float) SYM(g_hidden, hidden, float)
    SYM(g_wth, wth, __nv_bfloat16) SYM(g_wtl, wtl, __nv_bfloat16)
    #undef SYM

    cudaFuncSetAttribute(mma_gemm_kernel<0>, cudaFuncAttributeMaxDynamicSharedMemorySize, GK_SMEM);
    cudaFuncSetAttribute(mma_gemm_kernel<1>, cudaFuncAttributeMaxDynamicSharedMemorySize, GK_SMEM);
    cudaFuncSetAttribute(mma_gemm_kernel<2>, cudaFuncAttributeMaxDynamicSharedMemorySize, GK_SMEM);

    // 0. ONE prep launch: weight transposes/splits + CSR zero + detect + done-reset
    prep_all_kernel<<<(WT_TOTAL + 255) / 256, 256>>>(
        Wp, Wg, W1, W2, (const unsigned*)active);

    // 1. edge weights (per-edge, loops batches) + CSR counts + last-block scan
    edgew_kernel<<<CE / 256, 256>>>(es, ct_emb, ctype, esrc, edst, active, out_ew);

    // 2. h_route = elu(bt @ W_proj + b_proj)
    dim3 gP(1, M_ROWS / 128);
    mma_gemm_kernel<0><<<gP, 256, GK_SMEM>>>(
        bt, nullptr, 128, 128, wth + OFF_P, wtl + OFF_P, bp, hroute, 128, nullptr, nullptr);

    // 3. CSR fill + message gather
    fill_kernel<<<CE / 256, 256>>>(edst);
    messages_kernel<<<(CB * CNB * 32) / 256, 256>>>(out_ew, esrc);

    // 4. gated residual: x = bt + sigmoid(concat(bt,msg)@Wg + bg) * msg
    mma_gemm_kernel<1><<<gP, 256, GK_SMEM>>>(
        bt, msg, 128, 256, wth + OFF_G, wtl + OFF_G, bg, xbuf, 128, bt, msg);

    // 5. NL layers of LN + FFN
    dim3 gF1(2, M_ROWS / 128);
    for (int l = 0; l < CNL; l++) {
        ln_kernel<<<(M_ROWS * 32) / 256, 256>>>(xbuf, lns + l * CH, lnb + l * CH, normed);
        int o1 = (l == 0) ? OFF_W1A : OFF_W1B;
        int o2 = (l == 0) ? OFF_W2A : OFF_W2B;
        mma_gemm_kernel<0><<<gF1, 256, GK_SMEM>>>(
            normed, nullptr, 128, 128, wth + o1, wtl + o1, b1 + l * 256, hidden, 256, nullptr, nullptr);
        float* dst = (l == CNL - 1) ? out_x : xbuf;
        mma_gemm_kernel<2><<<gP, 256, GK_SMEM>>>(
            hidden, nullptr, 256, 256, wth + o2, wtl + o2, b2 + l * CH, dst, 128, xbuf, nullptr);
    }
    (void)in_sizes; (void)n_in; (void)out_size;
}

// round 15
// speedup vs baseline: 1.0245x; 1.0245x over previous
#include <cuda_runtime.h>
#include <cuda_bf16.h>
#include <math.h>
#include <stdint.h>

// Problem constants
#define CB   16
#define CNB  4096
#define CH   128
#define CE   65536
#define CNL  2
constexpr int M_ROWS = CB * CNB;          // 65536
constexpr int XSZ    = CB * CNB * CH;     // 8388608 (x portion of output)

// ---------------- scratch (device globals; no allocations allowed) ---------
__device__ __align__(16) float g_hroute[M_ROWS * CH];
__device__ __align__(16) float g_msg[M_ROWS * CH];
__device__ __align__(16) float g_x[M_ROWS * CH];
__device__ __align__(16) float g_normed[M_ROWS * CH];
__device__ __align__(16) float g_hidden[M_ROWS * 2 * CH];
__device__ int   g_cnt[CNB];
__device__ int   g_cur[CNB];
__device__ int   g_off[CNB + 1];
__device__ int   g_perm[CE];
__device__ int   g_active_bytes;
__device__ int   g_done;

// Pre-transposed/split weights: Wt[n*K + k] as bf16 hi + bf16 lo
constexpr int OFF_P   = 0;                 // N=128,K=128 (16384)
constexpr int OFF_G   = 16384;             // N=128,K=256 (32768)
constexpr int OFF_W1A = 49152;             // N=256,K=128 (32768)
constexpr int OFF_W1B = 81920;
constexpr int OFF_W2A = 114688;            // N=128,K=256 (32768)
constexpr int OFF_W2B = 147456;
constexpr int WT_TOTAL = 180224;
__device__ __align__(16) __nv_bfloat16 g_wth[WT_TOTAL];
__device__ __align__(16) __nv_bfloat16 g_wtl[WT_TOTAL];

// ---------------- helpers --------------------------------------------------
__device__ __forceinline__ float eluf(float v) { return v > 0.f ? v : expm1f(v); }
__device__ __forceinline__ float sigmoidf_(float v) { return 1.f / (1.f + expf(-v)); }

__device__ __forceinline__ bool active_at(const void* p, int idx) {
    if (g_active_bytes == 4) return ((const unsigned*)p)[idx] != 0u;
    return ((const unsigned char*)p)[idx] != 0;
}

// ---------------- fused prep: all weights + CSR zero + dtype detect --------
__global__ void prep_all_kernel(const float* __restrict__ Wp,
                                const float* __restrict__ Wg,
                                const float* __restrict__ W1,
                                const float* __restrict__ W2,
                                const unsigned* __restrict__ active) {
    int i = blockIdx.x * blockDim.x + threadIdx.x;

    // block 0: detect dtype width of block_active + reset done counter
    if (blockIdx.x == 0) {
        __shared__ int bad;
        if (threadIdx.x == 0) { bad = 0; g_done = 0; }
        __syncthreads();
        unsigned w = active[threadIdx.x];
        if (!(w == 0u || w == 1u || w == 0x3F800000u)) atomicAdd(&bad, 1);
        __syncthreads();
        if (threadIdx.x == 0) g_active_bytes = bad ? 1 : 4;
    }

    // CSR counter zeroing (same index space, low range)
    if (i < CNB) { g_cnt[i] = 0; g_cur[i] = 0; }

    if (i >= WT_TOTAL) return;
    // segment lookup (uniform per block: segments are >=16K elements)
    const float* W; int K, N, off;
    if (i < OFF_G)        { W = Wp;                K = 128; N = 128; off = OFF_P; }
    else if (i < OFF_W1A) { W = Wg;                K = 256; N = 128; off = OFF_G; }
    else if (i < OFF_W1B) { W = W1;                K = 128; N = 256; off = OFF_W1A; }
    else if (i < OFF_W2A) { W = W1 + 128 * 256;    K = 128; N = 256; off = OFF_W1B; }
    else if (i < OFF_W2B) { W = W2;                K = 256; N = 128; off = OFF_W2A; }
    else                  { W = W2 + 256 * 128;    K = 256; N = 128; off = OFF_W2B; }
    int li = i - off;
    int n = li / K, k = li - n * K;
    float v = W[(size_t)k * N + n];
    __nv_bfloat16 h = __float2bfloat16(v);
    g_wth[i] = h;
    g_wtl[i] = __float2bfloat16(v - __bfloat162float(h));
}

// ---------------- edge weights: one thread per EDGE, loop over batches -----
// Also builds CSR dst counts and the LAST finished block performs the scan.
__global__ void __launch_bounds__(256) edgew_kernel(
        const float* __restrict__ es,
        const float* __restrict__ ct_emb,
        const int* __restrict__ ctype,
        const int* __restrict__ esrc,
        const int* __restrict__ edst,
        const void* __restrict__ active,
        float* __restrict__ ew_out) {
    __shared__ int ct[CB];
    __shared__ int lastf;
    __shared__ int wsum[8];
    int tid = threadIdx.x;
    if (tid < CB) ct[tid] = ctype[tid];
    __syncthreads();

    int e = blockIdx.x * 256 + tid;   // e < CE (grid = CE/256)
    int src = esrc[e], dst = edst[e];
    atomicAdd(&g_cnt[dst], 1);
    float s = sigmoidf_(es[e]);
    #pragma unroll 4
    for (int b = 0; b < CB; b++) {
        float w = s * ct_emb[(size_t)ct[b] * CE + e];
        bool as = active_at(active, b * CNB + src);
        bool ad = active_at(active, b * CNB + dst);
        ew_out[(size_t)b * CE + e] = (as && ad) ? w : 0.f;
    }

    // ---- last-block CSR offset scan ----
    __threadfence();
    __syncthreads();
    if (tid == 0) lastf = (atomicAdd(&g_done, 1) == (int)gridDim.x - 1);
    __syncthreads();
    if (!lastf) return;

    int base = tid * 16;
    int v[16], sum = 0;
    #pragma unroll
    for (int q = 0; q < 16; q++) { v[q] = g_cnt[base + q]; sum += v[q]; }
    int lane = tid & 31, wrp = tid >> 5;
    int pre = sum;
    #pragma unroll
    for (int o = 1; o < 32; o <<= 1) {
        int x = __shfl_up_sync(0xffffffffu, pre, o);
        if (lane >= o) pre += x;
    }
    if (lane == 31) wsum[wrp] = pre;
    __syncthreads();
    if (wrp == 0) {
        int wv = (lane < 8) ? wsum[lane] : 0;
        #pragma unroll
        for (int o = 1; o < 8; o <<= 1) {
            int x = __shfl_up_sync(0xffffffffu, wv, o);
            if (lane >= o) wv += x;
        }
        if (lane < 8) wsum[lane] = wv;
    }
    __syncthreads();
    int excl = pre - sum + (wrp ? wsum[wrp - 1] : 0);   // exclusive prefix
    #pragma unroll
    for (int q = 0; q < 16; q++) { g_off[base + q] = excl; excl += v[q]; }
    if (tid == 255) g_off[CNB] = excl;
}

// ---------------- CSR fill --------------------------------------------------
__global__ void fill_kernel(const int* __restrict__ edst) {
    int e = blockIdx.x * blockDim.x + threadIdx.x;
    if (e >= CE) return;
    int d = edst[e];
    int pos = g_off[d] + atomicAdd(&g_cur[d], 1);
    g_perm[pos] = e;
}

// ---------------- message gather (one warp per (b, node)) ------------------
__global__ void messages_kernel(const float* __restrict__ edge_w,
                                const int* __restrict__ esrc) {
    int gw = (blockIdx.x * blockDim.x + threadIdx.x) >> 5;
    int lane = threadIdx.x & 31;
    if (gw >= CB * CNB) return;
    int b = gw >> 12;
    int n = gw & (CNB - 1);
    const float* hb  = g_hroute + (size_t)b * CNB * CH;
    const float* ewb = edge_w + (size_t)b * CE;
    float4 acc = make_float4(0.f, 0.f, 0.f, 0.f);
    int s = g_off[n], e = g_off[n + 1];
    for (int j = s; j < e; j++) {
        int eid = g_perm[j];
        float w = ewb[eid];
        const float4* src4 = (const float4*)(hb + (size_t)esrc[eid] * CH);
        float4 v = src4[lane];
        acc.x += w * v.x; acc.y += w * v.y; acc.z += w * v.z; acc.w += w * v.w;
    }
    ((float4*)(g_msg + (size_t)gw * CH))[lane] = acc;
}

// ---------------- LayerNorm ------------------------------------------------
__global__ void ln_kernel(const float* __restrict__ x,
                          const float* __restrict__ scale,
                          const float* __restrict__ bias,
                          float* __restrict__ out) {
    int row = (blockIdx.x * blockDim.x + threadIdx.x) >> 5;
    int lane = threadIdx.x & 31;
    if (row >= M_ROWS) return;
    const float4* xr = (const float4*)(x + (size_t)row * CH);
    float4 v = xr[lane];
    float s = v.x + v.y + v.z + v.w;
    #pragma unroll
    for (int o = 16; o; o >>= 1) s += __shfl_xor_sync(0xffffffffu, s, o);
    float mu = s * (1.f / CH);
    float dx = v.x - mu, dy = v.y - mu, dz = v.z - mu, dw = v.w - mu;
    float ss = dx * dx + dy * dy + dz * dz + dw * dw;
    #pragma unroll
    for (int o = 16; o; o >>= 1) ss += __shfl_xor_sync(0xffffffffu, ss, o);
    float inv = rsqrtf(ss * (1.f / CH) + 1e-5f);
    float4 sc = ((const float4*)scale)[lane];
    float4 bi = ((const float4*)bias)[lane];
    float4 o4;
    o4.x = dx * inv * sc.x + bi.x;
    o4.y = dy * inv * sc.y + bi.y;
    o4.z = dz * inv * sc.z + bi.z;
    o4.w = dw * inv * sc.w + bi.w;
    ((float4*)(out + (size_t)row * CH))[lane] = o4;
}

// ---------------- tensor-core GEMM (mma.sync, bf16 hi/lo, R6 schedule) -----
// C[M,N] = epi(A@Wt^T + bias), BM=BN=128, KC=64, 256 threads (8 warps),
// warp tile 32x64, m16n8k16. A: f32 load + in-loop hi/lo convert.
// B: pre-split bf16 uint4 fill.
// MODE 0: ELU   MODE 1: out = aux0 + sigmoid(v)*aux1   MODE 2: out = aux0 + v

__device__ __forceinline__ void mma16816(float* d, const uint32_t* a, const uint32_t* b) {
    asm volatile(
        "mma.sync.aligned.m16n8k16.row.col.f32.bf16.bf16.f32 "
        "{%0,%1,%2,%3}, {%4,%5,%6,%7}, {%8,%9}, {%0,%1,%2,%3};\n"
        : "+f"(d[0]), "+f"(d[1]), "+f"(d[2]), "+f"(d[3])
        : "r"(a[0]), "r"(a[1]), "r"(a[2]), "r"(a[3]), "r"(b[0]), "r"(b[1]));
}

constexpr int LDT   = 72;                   // padded row length (bf16 elems)
constexpr int GK_AH = 0;                    // 128 x 72 x 2B = 18432 each
constexpr int GK_AL = 18432;
constexpr int GK_BH = 36864;
constexpr int GK_BL = 55296;
constexpr int GK_SMEM = 73728;

template <int MODE>
__global__ void __launch_bounds__(256) mma_gemm_kernel(
    const float* __restrict__ A0, const float* __restrict__ A1, int K0, int K,
    const __nv_bfloat16* __restrict__ Wth, const __nv_bfloat16* __restrict__ Wtl,
    const float* __restrict__ bias,
    float* __restrict__ C, int N,
    const float* __restrict__ aux0, const float* __restrict__ aux1) {
    extern __shared__ __align__(16) char sm[];
    const int tid = threadIdx.x;
    const int wid = tid >> 5, lane = tid & 31;
    const int g = lane >> 2, tig = lane & 3;
    const int wm = (wid & 3) * 32, wn = (wid >> 2) * 64;
    const int bm = blockIdx.y * 128, bn = blockIdx.x * 128;

    float acc[2][8][4];
    #pragma unroll
    for (int i = 0; i < 2; i++)
        #pragma unroll
        for (int j = 0; j < 8; j++)
            #pragma unroll
            for (int q = 0; q < 4; q++) acc[i][j][q] = 0.f;

    for (int kc = 0; kc < K; kc += 64) {
        const float* Ap; int lda, kk;
        if (kc < K0) { Ap = A0; lda = K0; kk = kc; }
        else         { Ap = A1; lda = K - K0; kk = kc - K0; }
        // A tile: 128 rows x 64 cols fp32 -> bf16 hi/lo in SMEM
        #pragma unroll
        for (int it = 0; it < 8; it++) {
            int i = tid + it * 256;
            int row = i >> 4, c4 = (i & 15) << 2;
            float4 v = *(const float4*)(Ap + (size_t)(bm + row) * lda + kk + c4);
            __nv_bfloat162 h0, h1, l0, l1;
            h0.x = __float2bfloat16(v.x); h0.y = __float2bfloat16(v.y);
            h1.x = __float2bfloat16(v.z); h1.y = __float2bfloat16(v.w);
            l0.x = __float2bfloat16(v.x - __bfloat162float(h0.x));
            l0.y = __float2bfloat16(v.y - __bfloat162float(h0.y));
            l1.x = __float2bfloat16(v.z - __bfloat162float(h1.x));
            l1.y = __float2bfloat16(v.w - __bfloat162float(h1.y));
            int off = (row * LDT + c4) * 2;
            *(__nv_bfloat162*)(sm + GK_AH + off)     = h0;
            *(__nv_bfloat162*)(sm + GK_AH + off + 4) = h1;
            *(__nv_bfloat162*)(sm + GK_AL + off)     = l0;
            *(__nv_bfloat162*)(sm + GK_AL + off + 4) = l1;
        }
        // B tile: 128 n-rows x 64 k-cols, pre-split bf16, uint4 moves
        #pragma unroll
        for (int it = 0; it < 4; it++) {
            int i = tid + it * 256;
            int n = i >> 3, k8 = (i & 7) << 3;
            size_t src = (size_t)(bn + n) * K + kc + k8;
            int off = (n * LDT + k8) * 2;
            *(uint4*)(sm + GK_BH + off) = *(const uint4*)(Wth + src);
            *(uint4*)(sm + GK_BL + off) = *(const uint4*)(Wtl + src);
        }
        __syncthreads();

        #pragma unroll
        for (int ks = 0; ks < 4; ks++) {
            int k0 = ks << 4;
            uint32_t ah[2][4], al[2][4];
            #pragma unroll
            for (int mt = 0; mt < 2; mt++) {
                int r0 = wm + mt * 16 + g;
                int o0 = (r0 * LDT + k0 + tig * 2) * 2;
                int o1 = ((r0 + 8) * LDT + k0 + tig * 2) * 2;
                ah[mt][0] = *(const uint32_t*)(sm + GK_AH + o0);
                ah[mt][1] = *(const uint32_t*)(sm + GK_AH + o1);
                ah[mt][2] = *(const uint32_t*)(sm + GK_AH + o0 + 16);
                ah[mt][3] = *(const uint32_t*)(sm + GK_AH + o1 + 16);
                al[mt][0] = *(const uint32_t*)(sm + GK_AL + o0);
                al[mt][1] = *(const uint32_t*)(sm + GK_AL + o1);
                al[mt][2] = *(const uint32_t*)(sm + GK_AL + o0 + 16);
                al[mt][3] = *(const uint32_t*)(sm + GK_AL + o1 + 16);
            }
            #pragma unroll
            for (int nt = 0; nt < 8; nt++) {
                int nb = wn + nt * 8 + g;
                int ob = (nb * LDT + k0 + tig * 2) * 2;
                uint32_t bh[2], bl[2];
                bh[0] = *(const uint32_t*)(sm + GK_BH + ob);
                bh[1] = *(const uint32_t*)(sm + GK_BH + ob + 16);
                bl[0] = *(const uint32_t*)(sm + GK_BL + ob);
                bl[1] = *(const uint32_t*)(sm + GK_BL + ob + 16);
                #pragma unroll
                for (int mt = 0; mt < 2; mt++) {
                    mma16816(acc[mt][nt], ah[mt], bh);
                    mma16816(acc[mt][nt], ah[mt], bl);
                    mma16816(acc[mt][nt], al[mt], bh);
                }
            }
        }
        __syncthreads();
    }

    // epilogue: c0,c1 -> row g; c2,c3 -> row g+8; cols tig*2, tig*2+1
    #pragma unroll
    for (int mt = 0; mt < 2; mt++) {
        #pragma unroll
        for (int half = 0; half < 2; half++) {
            int r = bm + wm + mt * 16 + g + half * 8;
            #pragma unroll
            for (int nt = 0; nt < 8; nt++) {
                int col = bn + wn + nt * 8 + tig * 2;
                float v0 = acc[mt][nt][half * 2 + 0];
                float v1 = acc[mt][nt][half * 2 + 1];
                float2 bv = *(const float2*)(bias + col);
                v0 += bv.x; v1 += bv.y;
                size_t idx = (size_t)r * N + col;
                if (MODE == 0) {
                    v0 = eluf(v0); v1 = eluf(v1);
                } else if (MODE == 1) {
                    float2 a0v = *(const float2*)(aux0 + idx);
                    float2 a1v = *(const float2*)(aux1 + idx);
                    v0 = a0v.x + sigmoidf_(v0) * a1v.x;
                    v1 = a0v.y + sigmoidf_(v1) * a1v.y;
                } else {
                    float2 a0v = *(const float2*)(aux0 + idx);
                    v0 = a0v.x + v0; v1 = a0v.y + v1;
                }
                *(float2*)(C + idx) = make_float2(v0, v1);
            }
        }
    }
}

// ---------------- launch ----------------------------------------------------
extern "C" void kernel_launch(void* const* d_in, const int* in_sizes, int n_in,
                              void* d_out, int out_size) {
    const float* bt     = (const float*)d_in[0];
    const float* es     = (const float*)d_in[1];
    const float* ct_emb = (const float*)d_in[2];
    const float* Wp     = (const float*)d_in[3];
    const float* bp     = (const float*)d_in[4];
    const float* Wg     = (const float*)d_in[5];
    const float* bg     = (const float*)d_in[6];
    const float* lns    = (const float*)d_in[7];
    const float* lnb    = (const float*)d_in[8];
    const float* W1     = (const float*)d_in[9];
    const float* b1     = (const float*)d_in[10];
    const float* W2     = (const float*)d_in[11];
    const float* b2     = (const float*)d_in[12];
    const int*   ctype  = (const int*)d_in[13];
    const int*   esrc   = (const int*)d_in[14];
    const int*   edst   = (const int*)d_in[15];
    const void*  active = d_in[16];

    float* out_x  = (float*)d_out;
    float* out_ew = out_x + XSZ;

    void *pv;
    #define SYM(name, var, type) cudaGetSymbolAddress(&pv, name); type* var = (type*)pv;
    SYM(g_hroute, hroute, float) SYM(g_msg, msg, float)
    SYM(g_x, xbuf, float) SYM(g_normed, normed, float) SYM(g_hidden, hidden, float)
    SYM(g_wth, wth, __nv_bfloat16) SYM(g_wtl, wtl, __nv_bfloat16)
    #undef SYM

    cudaFuncSetAttribute(mma_gemm_kernel<0>, cudaFuncAttributeMaxDynamicSharedMemorySize, GK_SMEM);
    cudaFuncSetAttribute(mma_gemm_kernel<1>, cudaFuncAttributeMaxDynamicSharedMemorySize, GK_SMEM);
    cudaFuncSetAttribute(mma_gemm_kernel<2>, cudaFuncAttributeMaxDynamicSharedMemorySize, GK_SMEM);

    // side stream + fork/join events (host-side resources only; kernel_launch
    // is invoked a bounded number of times — correctness + capture)
    cudaStream_t s2;
    cudaStreamCreateWithFlags(&s2, cudaStreamNonBlocking);
    cudaEvent_t evFork, evJoin;
    cudaEventCreateWithFlags(&evFork, cudaEventDisableTiming);
    cudaEventCreateWithFlags(&evJoin, cudaEventDisableTiming);

    // 0. ONE prep launch: weight transposes/splits + CSR zero + detect
    prep_all_kernel<<<(WT_TOTAL + 255) / 256, 256>>>(
        Wp, Wg, W1, W2, (const unsigned*)active);

    // fork: CSR/edge path on s2, concurrent with the P-GEMM on main stream
    cudaEventRecord(evFork, 0);
    cudaStreamWaitEvent(s2, evFork, 0);

    // 1. (s2) edge weights + CSR counts + last-block scan, then fill
    edgew_kernel<<<CE / 256, 256, 0, s2>>>(es, ct_emb, ctype, esrc, edst, active, out_ew);
    fill_kernel<<<CE / 256, 256, 0, s2>>>(edst);
    cudaEventRecord(evJoin, s2);

    // 2. (main) h_route = elu(bt @ W_proj + b_proj)
    dim3 gP(1, M_ROWS / 128);
    mma_gemm_kernel<0><<<gP, 256, GK_SMEM>>>(
        bt, nullptr, 128, 128, wth + OFF_P, wtl + OFF_P, bp, hroute, 128, nullptr, nullptr);

    // join: messages needs hroute (main) + perm/off/edge_w (s2)
    cudaStreamWaitEvent(0, evJoin, 0);

    // 3. message gather
    messages_kernel<<<(CB * CNB * 32) / 256, 256>>>(out_ew, esrc);

    // 4. gated residual: x = bt + sigmoid(concat(bt,msg)@Wg + bg) * msg
    mma_gemm_kernel<1><<<gP, 256, GK_SMEM>>>(
        bt, msg, 128, 256, wth + OFF_G, wtl + OFF_G, bg, xbuf, 128, bt, msg);

    // 5. NL layers of LN + FFN
    dim3 gF1(2, M_ROWS / 128);
    for (int l = 0; l < CNL; l++) {
        ln_kernel<<<(M_ROWS * 32) / 256, 256>>>(xbuf, lns + l * CH, lnb + l * CH, normed);
        int o1 = (l == 0) ? OFF_W1A : OFF_W1B;
        int o2 = (l == 0) ? OFF_W2A : OFF_W2B;
        mma_gemm_kernel<0><<<gF1, 256, GK_SMEM>>>(
            normed, nullptr, 128, 128, wth + o1, wtl + o1, b1 + l * 256, hidden, 256, nullptr, nullptr);
        float* dst = (l == CNL - 1) ? out_x : xbuf;
        mma_gemm_kernel<2><<<gP, 256, GK_SMEM>>>(
            hidden, nullptr, 256, 256, wth + o2, wtl + o2, b2 + l * CH, dst, 128, xbuf, nullptr);
    }
    (void)in_sizes; (void)n_in; (void)out_size;
}